// round 13
// baseline (speedup 1.0000x reference)
#include <cuda_runtime.h>
#include <cuda_fp16.h>
#include <cstdint>

// TriPlane bilinear sampling, GB300 — round 13.
// R11 sampler shape (16 lanes/point, LDG.64 = 2 lines/instr) + 2-point
// software pipeline per thread: both points' 24 loads issued before any
// consumption -> ~2x bytes in flight to hide L2 latency.

#define NPTS   1048576
#define RES    256
#define FEAT   64
#define PLANE_ELEMS (RES * RES * FEAT)

__device__ __half g_tp16[3 * PLANE_ELEMS];

// ---------------------------------------------------------------------------
__global__ __launch_bounds__(256) void transpose_kernel(
    const float* __restrict__ p0,
    const float* __restrict__ p1,
    const float* __restrict__ p2)
{
    __shared__ float tile[FEAT][33];
    const int x0    = blockIdx.x * 32;
    const int y     = blockIdx.y;
    const int plane = blockIdx.z;
    const int tid   = threadIdx.x;

    const float* src = (plane == 0) ? p0 : (plane == 1) ? p1 : p2;

    #pragma unroll
    for (int i = 0; i < 2; i++) {
        int gidx = tid + i * 256;
        int c    = gidx >> 3;
        int x4   = gidx & 7;
        float4 v = __ldg((const float4*)(src + c * (RES * RES) + y * RES + x0) + x4);
        tile[c][x4 * 4 + 0] = v.x;
        tile[c][x4 * 4 + 1] = v.y;
        tile[c][x4 * 4 + 2] = v.z;
        tile[c][x4 * 4 + 3] = v.w;
    }
    __syncthreads();

    __half* dst = g_tp16 + plane * PLANE_ELEMS;
    #pragma unroll
    for (int i = 0; i < 4; i++) {
        int idx = tid + i * 256;
        int xx = idx >> 5;
        int cp = idx & 31;
        float2 f = make_float2(tile[2 * cp][xx], tile[2 * cp + 1][xx]);
        ((half2*)(dst + ((y * RES + (x0 + xx)) * FEAT)))[cp] = __float22half2_rn(f);
    }
}

// ---------------------------------------------------------------------------
__device__ __forceinline__ void plane_setup(float u, float v,
                                            int& t00, half2 w[4]) {
    float ix = (u + 1.0f) * 0.5f * (float)(RES - 1);
    float iy = (v + 1.0f) * 0.5f * (float)(RES - 1);
    float fx0 = floorf(ix);
    float fy0 = floorf(iy);

    float wx1 = ix - fx0;
    float wx0 = (fx0 + 1.0f) - ix;
    float wy1 = iy - fy0;
    float wy0 = (fy0 + 1.0f) - iy;

    int x0 = (int)fx0;               // u,v in [-1,1): no clamps needed
    int y0 = (int)fy0;
    t00 = (y0 << 12) + (x0 << 4);    // uint2 offset of texel (y0,x0)

    w[0] = __float2half2_rn(wx0 * wy0);
    w[1] = __float2half2_rn(wx1 * wy0);
    w[2] = __float2half2_rn(wx0 * wy1);
    w[3] = __float2half2_rn(wx1 * wy1);
}

__device__ __forceinline__ void plane_reduce(const uint2& r00, const uint2& r01,
                                             const uint2& r10, const uint2& r11,
                                             const half2 w[4], half2 acc[2]) {
    const half2* h00 = (const half2*)&r00;
    const half2* h01 = (const half2*)&r01;
    const half2* h10 = (const half2*)&r10;
    const half2* h11 = (const half2*)&r11;
    #pragma unroll
    for (int j = 0; j < 2; j++) {
        half2 a = acc[j];
        a = __hfma2(w[0], h00[j], a);
        a = __hfma2(w[1], h01[j], a);
        a = __hfma2(w[2], h10[j], a);
        a = __hfma2(w[3], h11[j], a);
        acc[j] = a;
    }
}

// Issue the 12 loads for one point.
#define ISSUE_LOADS(q, r)                                                     \
    r[0]  = __ldg(q##A);        r[1]  = __ldg(q##A + 16);                     \
    r[2]  = __ldg(q##A + 4096); r[3]  = __ldg(q##A + 4112);                   \
    r[4]  = __ldg(q##B);        r[5]  = __ldg(q##B + 16);                     \
    r[6]  = __ldg(q##B + 4096); r[7]  = __ldg(q##B + 4112);                   \
    r[8]  = __ldg(q##C);        r[9]  = __ldg(q##C + 16);                     \
    r[10] = __ldg(q##C + 4096); r[11] = __ldg(q##C + 4112);

__global__ __launch_bounds__(256, 3) void sample_kernel(const float* __restrict__ x,
                                                        float* __restrict__ out) {
    const int gtid = blockIdx.x * blockDim.x + threadIdx.x;
    const int slot = gtid >> 4;       // 16 lanes per slot; slot handles 2 points
    const int sub  = gtid & 15;
    const int p0   = slot * 2;
    const int p1   = p0 + 1;

    const half2* g0 = (const half2*)0;  (void)g0;

    // ---- point 0 setup + loads ----
    float ax = __ldg(x + 3 * p0 + 0);
    float ay = __ldg(x + 3 * p0 + 1);
    float az = __ldg(x + 3 * p0 + 2);
    int t0A, t0B, t0C;
    half2 w0A[4], w0B[4], w0C[4];
    plane_setup(ax, ay, t0A, w0A);
    plane_setup(ax, az, t0B, w0B);
    plane_setup(ay, az, t0C, w0C);
    const uint2* q0A = (const uint2*)(g_tp16 + 0 * PLANE_ELEMS) + sub + t0A;
    const uint2* q0B = (const uint2*)(g_tp16 + 1 * PLANE_ELEMS) + sub + t0B;
    const uint2* q0C = (const uint2*)(g_tp16 + 2 * PLANE_ELEMS) + sub + t0C;
    uint2 r0[12];
    ISSUE_LOADS(q0, r0)

    // ---- point 1 setup + loads (while point 0 loads are in flight) ----
    float bx = __ldg(x + 3 * p1 + 0);
    float by = __ldg(x + 3 * p1 + 1);
    float bz = __ldg(x + 3 * p1 + 2);
    int t1A, t1B, t1C;
    half2 w1A[4], w1B[4], w1C[4];
    plane_setup(bx, by, t1A, w1A);
    plane_setup(bx, bz, t1B, w1B);
    plane_setup(by, bz, t1C, w1C);
    const uint2* q1A = (const uint2*)(g_tp16 + 0 * PLANE_ELEMS) + sub + t1A;
    const uint2* q1B = (const uint2*)(g_tp16 + 1 * PLANE_ELEMS) + sub + t1B;
    const uint2* q1C = (const uint2*)(g_tp16 + 2 * PLANE_ELEMS) + sub + t1C;
    uint2 r1[12];
    ISSUE_LOADS(q1, r1)

    const float inv3 = 1.0f / 3.0f;

    // ---- consume point 0 ----
    {
        half2 acc[2];
        acc[0] = __float2half2_rn(0.0f);
        acc[1] = __float2half2_rn(0.0f);
        plane_reduce(r0[0], r0[1], r0[2], r0[3],  w0A, acc);
        plane_reduce(r0[4], r0[5], r0[6], r0[7],  w0B, acc);
        plane_reduce(r0[8], r0[9], r0[10], r0[11], w0C, acc);
        float2 f0 = __half22float2(acc[0]);
        float2 f1 = __half22float2(acc[1]);
        float4 o = make_float4(f0.x * inv3, f0.y * inv3, f1.x * inv3, f1.y * inv3);
        ((float4*)(out + p0 * FEAT))[sub] = o;
    }

    // ---- consume point 1 ----
    {
        half2 acc[2];
        acc[0] = __float2half2_rn(0.0f);
        acc[1] = __float2half2_rn(0.0f);
        plane_reduce(r1[0], r1[1], r1[2], r1[3],  w1A, acc);
        plane_reduce(r1[4], r1[5], r1[6], r1[7],  w1B, acc);
        plane_reduce(r1[8], r1[9], r1[10], r1[11], w1C, acc);
        float2 f0 = __half22float2(acc[0]);
        float2 f1 = __half22float2(acc[1]);
        float4 o = make_float4(f0.x * inv3, f0.y * inv3, f1.x * inv3, f1.y * inv3);
        ((float4*)(out + p1 * FEAT))[sub] = o;
    }
}

// ---------------------------------------------------------------------------
extern "C" void kernel_launch(void* const* d_in, const int* in_sizes, int n_in,
                              void* d_out, int out_size) {
    const float* x        = (const float*)d_in[0];
    const float* plane_xy = (const float*)d_in[1];
    const float* plane_xz = (const float*)d_in[2];
    const float* plane_yz = (const float*)d_in[3];
    float* out = (float*)d_out;

    dim3 tgrid(RES / 32, RES, 3);
    transpose_kernel<<<tgrid, 256>>>(plane_xy, plane_xz, plane_yz);

    const int threads = 256;
    const int blocks  = (NPTS * 8) / threads;   // 16 lanes x (NPTS/2) slots
    sample_kernel<<<blocks, threads>>>(x, out);
}

// round 14
// speedup vs baseline: 1.1842x; 1.1842x over previous
#include <cuda_runtime.h>
#include <cuda_fp16.h>
#include <cstdint>

// TriPlane bilinear sampling, GB300 — round 14 (R11 polish).
// - 16 lanes/point, LDG.64 (2 lines/instr), 12 loads upfront, half2 accum.
// - Coordinate setup (ix/floor/frac) computed once per axis, not per plane.
// - 1/3 factor folded into the fp16 plane data at transpose time.

#define NPTS   1048576
#define RES    256
#define FEAT   64
#define PLANE_ELEMS (RES * RES * FEAT)

__device__ __half g_tp16[3 * PLANE_ELEMS];

// ---------------------------------------------------------------------------
// Transpose + f32->fp16 convert + pre-scale by 1/3.
// ---------------------------------------------------------------------------
__global__ __launch_bounds__(256) void transpose_kernel(
    const float* __restrict__ p0,
    const float* __restrict__ p1,
    const float* __restrict__ p2)
{
    __shared__ float tile[FEAT][33];
    const int x0    = blockIdx.x * 32;
    const int y     = blockIdx.y;
    const int plane = blockIdx.z;
    const int tid   = threadIdx.x;

    const float* src = (plane == 0) ? p0 : (plane == 1) ? p1 : p2;
    const float s = 1.0f / 3.0f;

    #pragma unroll
    for (int i = 0; i < 2; i++) {
        int gidx = tid + i * 256;
        int c    = gidx >> 3;
        int x4   = gidx & 7;
        float4 v = __ldg((const float4*)(src + c * (RES * RES) + y * RES + x0) + x4);
        tile[c][x4 * 4 + 0] = v.x * s;
        tile[c][x4 * 4 + 1] = v.y * s;
        tile[c][x4 * 4 + 2] = v.z * s;
        tile[c][x4 * 4 + 3] = v.w * s;
    }
    __syncthreads();

    __half* dst = g_tp16 + plane * PLANE_ELEMS;
    #pragma unroll
    for (int i = 0; i < 4; i++) {
        int idx = tid + i * 256;
        int xx = idx >> 5;
        int cp = idx & 31;
        float2 f = make_float2(tile[2 * cp][xx], tile[2 * cp + 1][xx]);
        ((half2*)(dst + ((y * RES + (x0 + xx)) * FEAT)))[cp] = __float22half2_rn(f);
    }
}

// ---------------------------------------------------------------------------
__device__ __forceinline__ void plane_reduce(const uint2& r00, const uint2& r01,
                                             const uint2& r10, const uint2& r11,
                                             const half2 w[4], half2 acc[2]) {
    const half2* h00 = (const half2*)&r00;
    const half2* h01 = (const half2*)&r01;
    const half2* h10 = (const half2*)&r10;
    const half2* h11 = (const half2*)&r11;
    #pragma unroll
    for (int j = 0; j < 2; j++) {
        half2 a = acc[j];
        a = __hfma2(w[0], h00[j], a);
        a = __hfma2(w[1], h01[j], a);
        a = __hfma2(w[2], h10[j], a);
        a = __hfma2(w[3], h11[j], a);
        acc[j] = a;
    }
}

__global__ __launch_bounds__(256) void sample_kernel(const float* __restrict__ x,
                                                     float* __restrict__ out) {
    const int gtid = blockIdx.x * blockDim.x + threadIdx.x;
    const int p    = gtid >> 4;       // point index (16 lanes/point)
    const int sub  = gtid & 15;       // 4-channel group

    const float px = __ldg(x + 3 * p + 0);
    const float py = __ldg(x + 3 * p + 1);
    const float pz = __ldg(x + 3 * p + 2);

    // --- shared per-axis setup (once, not per plane) ---
    float ix = fmaf(px, 127.5f, 127.5f);
    float iy = fmaf(py, 127.5f, 127.5f);
    float iz = fmaf(pz, 127.5f, 127.5f);
    float fx = floorf(ix), fy = floorf(iy), fz = floorf(iz);
    float dx1 = ix - fx, dy1 = iy - fy, dz1 = iz - fz;
    float dx0 = 1.0f - dx1, dy0 = 1.0f - dy1, dz0 = 1.0f - dz1;
    int xi = (int)fx, yi = (int)fy, zi = (int)fz;   // coords in [-1,1): no clamps

    // uint2 texel offsets: (row<<12) + (col<<4)
    int tA = (yi << 12) + (xi << 4);   // plane xy: row=y, col=x
    int tB = (zi << 12) + (xi << 4);   // plane xz: row=z, col=x
    int tC = (zi << 12) + (yi << 4);   // plane yz: row=z, col=y

    half2 wA[4], wB[4], wC[4];
    wA[0] = __float2half2_rn(dx0 * dy0);
    wA[1] = __float2half2_rn(dx1 * dy0);
    wA[2] = __float2half2_rn(dx0 * dy1);
    wA[3] = __float2half2_rn(dx1 * dy1);
    wB[0] = __float2half2_rn(dx0 * dz0);
    wB[1] = __float2half2_rn(dx1 * dz0);
    wB[2] = __float2half2_rn(dx0 * dz1);
    wB[3] = __float2half2_rn(dx1 * dz1);
    wC[0] = __float2half2_rn(dy0 * dz0);
    wC[1] = __float2half2_rn(dy1 * dz0);
    wC[2] = __float2half2_rn(dy0 * dz1);
    wC[3] = __float2half2_rn(dy1 * dz1);

    const uint2* qA = (const uint2*)(g_tp16 + 0 * PLANE_ELEMS) + sub + tA;
    const uint2* qB = (const uint2*)(g_tp16 + 1 * PLANE_ELEMS) + sub + tB;
    const uint2* qC = (const uint2*)(g_tp16 + 2 * PLANE_ELEMS) + sub + tC;

    // All 12 loads issued before any consumption (MLP = 12).
    uint2 ra0 = __ldg(qA);
    uint2 ra1 = __ldg(qA + 16);
    uint2 ra2 = __ldg(qA + 4096);
    uint2 ra3 = __ldg(qA + 4112);
    uint2 rb0 = __ldg(qB);
    uint2 rb1 = __ldg(qB + 16);
    uint2 rb2 = __ldg(qB + 4096);
    uint2 rb3 = __ldg(qB + 4112);
    uint2 rc0 = __ldg(qC);
    uint2 rc1 = __ldg(qC + 16);
    uint2 rc2 = __ldg(qC + 4096);
    uint2 rc3 = __ldg(qC + 4112);

    half2 acc[2];
    acc[0] = __float2half2_rn(0.0f);
    acc[1] = __float2half2_rn(0.0f);

    plane_reduce(ra0, ra1, ra2, ra3, wA, acc);
    plane_reduce(rb0, rb1, rb2, rb3, wB, acc);
    plane_reduce(rc0, rc1, rc2, rc3, wC, acc);

    // 1/3 already folded into plane data.
    float2 f0 = __half22float2(acc[0]);
    float2 f1 = __half22float2(acc[1]);
    float4 o = make_float4(f0.x, f0.y, f1.x, f1.y);
    ((float4*)(out + p * FEAT))[sub] = o;
}

// ---------------------------------------------------------------------------
extern "C" void kernel_launch(void* const* d_in, const int* in_sizes, int n_in,
                              void* d_out, int out_size) {
    const float* x        = (const float*)d_in[0];
    const float* plane_xy = (const float*)d_in[1];
    const float* plane_xz = (const float*)d_in[2];
    const float* plane_yz = (const float*)d_in[3];
    float* out = (float*)d_out;

    dim3 tgrid(RES / 32, RES, 3);
    transpose_kernel<<<tgrid, 256>>>(plane_xy, plane_xz, plane_yz);

    const int threads = 256;
    const int blocks  = (NPTS * 16) / threads;   // 16 lanes per point
    sample_kernel<<<blocks, threads>>>(x, out);
}

// round 15
// speedup vs baseline: 1.1849x; 1.0006x over previous
#include <cuda_runtime.h>
#include <cuda_fp16.h>
#include <cstdint>

// TriPlane bilinear sampling, GB300 — round 15.
// R14 + load-first scheduling: issue all 12 LDG.64 immediately after the
// (minimal) index chain; compute the 12 weight half2s while loads fly.
// Max-L1 carveout hint for the smem-free sampler.

#define NPTS   1048576
#define RES    256
#define FEAT   64
#define PLANE_ELEMS (RES * RES * FEAT)

__device__ __half g_tp16[3 * PLANE_ELEMS];

// ---------------------------------------------------------------------------
// Transpose + f32->fp16 convert + pre-scale by 1/3. 2 rows per block.
// grid: (8, 128, 3), block 256.
// ---------------------------------------------------------------------------
__global__ __launch_bounds__(256) void transpose_kernel(
    const float* __restrict__ p0,
    const float* __restrict__ p1,
    const float* __restrict__ p2)
{
    __shared__ float tile[2][FEAT][33];
    const int x0    = blockIdx.x * 32;
    const int y0    = blockIdx.y * 2;
    const int plane = blockIdx.z;
    const int tid   = threadIdx.x;

    const float* src = (plane == 0) ? p0 : (plane == 1) ? p1 : p2;
    const float s = 1.0f / 3.0f;

    #pragma unroll
    for (int r = 0; r < 2; r++) {
        #pragma unroll
        for (int i = 0; i < 2; i++) {
            int gidx = tid + i * 256;
            int c    = gidx >> 3;
            int x4   = gidx & 7;
            float4 v = __ldg((const float4*)(src + c * (RES * RES) + (y0 + r) * RES + x0) + x4);
            tile[r][c][x4 * 4 + 0] = v.x * s;
            tile[r][c][x4 * 4 + 1] = v.y * s;
            tile[r][c][x4 * 4 + 2] = v.z * s;
            tile[r][c][x4 * 4 + 3] = v.w * s;
        }
    }
    __syncthreads();

    __half* dst = g_tp16 + plane * PLANE_ELEMS;
    #pragma unroll
    for (int r = 0; r < 2; r++) {
        #pragma unroll
        for (int i = 0; i < 4; i++) {
            int idx = tid + i * 256;
            int xx = idx >> 5;
            int cp = idx & 31;
            float2 f = make_float2(tile[r][2 * cp][xx], tile[r][2 * cp + 1][xx]);
            ((half2*)(dst + (((y0 + r) * RES + (x0 + xx)) * FEAT)))[cp] = __float22half2_rn(f);
        }
    }
}

// ---------------------------------------------------------------------------
__device__ __forceinline__ void plane_reduce(const uint2& r00, const uint2& r01,
                                             const uint2& r10, const uint2& r11,
                                             const half2 w[4], half2 acc[2]) {
    const half2* h00 = (const half2*)&r00;
    const half2* h01 = (const half2*)&r01;
    const half2* h10 = (const half2*)&r10;
    const half2* h11 = (const half2*)&r11;
    #pragma unroll
    for (int j = 0; j < 2; j++) {
        half2 a = acc[j];
        a = __hfma2(w[0], h00[j], a);
        a = __hfma2(w[1], h01[j], a);
        a = __hfma2(w[2], h10[j], a);
        a = __hfma2(w[3], h11[j], a);
        acc[j] = a;
    }
}

__global__ __launch_bounds__(256) void sample_kernel(const float* __restrict__ x,
                                                     float* __restrict__ out) {
    const int gtid = blockIdx.x * blockDim.x + threadIdx.x;
    const int p    = gtid >> 4;       // point index (16 lanes/point)
    const int sub  = gtid & 15;       // 4-channel group

    const float px = __ldg(x + 3 * p + 0);
    const float py = __ldg(x + 3 * p + 1);
    const float pz = __ldg(x + 3 * p + 2);

    // --- minimal index chain first ---
    float ix = fmaf(px, 127.5f, 127.5f);
    float iy = fmaf(py, 127.5f, 127.5f);
    float iz = fmaf(pz, 127.5f, 127.5f);
    float fx = floorf(ix), fy = floorf(iy), fz = floorf(iz);
    int xi = (int)fx, yi = (int)fy, zi = (int)fz;   // coords in [-1,1): no clamps

    int tA = (yi << 12) + (xi << 4);   // plane xy: row=y, col=x  (uint2 units)
    int tB = (zi << 12) + (xi << 4);   // plane xz: row=z, col=x
    int tC = (zi << 12) + (yi << 4);   // plane yz: row=z, col=y

    const uint2* qA = (const uint2*)(g_tp16 + 0 * PLANE_ELEMS) + sub + tA;
    const uint2* qB = (const uint2*)(g_tp16 + 1 * PLANE_ELEMS) + sub + tB;
    const uint2* qC = (const uint2*)(g_tp16 + 2 * PLANE_ELEMS) + sub + tC;

    // --- issue all 12 loads ASAP ---
    uint2 ra0 = __ldg(qA);
    uint2 ra1 = __ldg(qA + 16);
    uint2 ra2 = __ldg(qA + 4096);
    uint2 ra3 = __ldg(qA + 4112);
    uint2 rb0 = __ldg(qB);
    uint2 rb1 = __ldg(qB + 16);
    uint2 rb2 = __ldg(qB + 4096);
    uint2 rb3 = __ldg(qB + 4112);
    uint2 rc0 = __ldg(qC);
    uint2 rc1 = __ldg(qC + 16);
    uint2 rc2 = __ldg(qC + 4096);
    uint2 rc3 = __ldg(qC + 4112);

    // --- weights computed while loads are in flight ---
    float dx1 = ix - fx, dy1 = iy - fy, dz1 = iz - fz;
    float dx0 = 1.0f - dx1, dy0 = 1.0f - dy1, dz0 = 1.0f - dz1;

    half2 wA[4], wB[4], wC[4];
    wA[0] = __float2half2_rn(dx0 * dy0);
    wA[1] = __float2half2_rn(dx1 * dy0);
    wA[2] = __float2half2_rn(dx0 * dy1);
    wA[3] = __float2half2_rn(dx1 * dy1);
    wB[0] = __float2half2_rn(dx0 * dz0);
    wB[1] = __float2half2_rn(dx1 * dz0);
    wB[2] = __float2half2_rn(dx0 * dz1);
    wB[3] = __float2half2_rn(dx1 * dz1);
    wC[0] = __float2half2_rn(dy0 * dz0);
    wC[1] = __float2half2_rn(dy1 * dz0);
    wC[2] = __float2half2_rn(dy0 * dz1);
    wC[3] = __float2half2_rn(dy1 * dz1);

    half2 acc[2];
    acc[0] = __float2half2_rn(0.0f);
    acc[1] = __float2half2_rn(0.0f);

    plane_reduce(ra0, ra1, ra2, ra3, wA, acc);
    plane_reduce(rb0, rb1, rb2, rb3, wB, acc);
    plane_reduce(rc0, rc1, rc2, rc3, wC, acc);

    // 1/3 already folded into plane data.
    float2 f0 = __half22float2(acc[0]);
    float2 f1 = __half22float2(acc[1]);
    float4 o = make_float4(f0.x, f0.y, f1.x, f1.y);
    ((float4*)(out + p * FEAT))[sub] = o;
}

// ---------------------------------------------------------------------------
extern "C" void kernel_launch(void* const* d_in, const int* in_sizes, int n_in,
                              void* d_out, int out_size) {
    const float* x        = (const float*)d_in[0];
    const float* plane_xy = (const float*)d_in[1];
    const float* plane_xz = (const float*)d_in[2];
    const float* plane_yz = (const float*)d_in[3];
    float* out = (float*)d_out;

    // Prefer max L1 cache for the smem-free sampler (host-side attribute,
    // no stream work — graph-capture safe). Idempotent across calls.
    static int carveout_set = 0;
    if (!carveout_set) {
        cudaFuncSetAttribute(sample_kernel,
                             cudaFuncAttributePreferredSharedMemoryCarveout,
                             cudaSharedmemCarveoutMaxL1);
        carveout_set = 1;
    }

    dim3 tgrid(RES / 32, RES / 2, 3);
    transpose_kernel<<<tgrid, 256>>>(plane_xy, plane_xz, plane_yz);

    const int threads = 256;
    const int blocks  = (NPTS * 16) / threads;   // 16 lanes per point
    sample_kernel<<<blocks, threads>>>(x, out);
}